// round 16
// baseline (speedup 1.0000x reference)
#include <cuda_runtime.h>
#include <cuda_fp16.h>
#include <cstdint>

#define NB   8
#define HH   64
#define WWD  64
#define LQ   4096
#define CHN  256
#define NCAT 384
#define MROWS (NB * LQ)           // 32768
#define KDIM 256
#define PADK 40                   // A fp32 smem row stride (floats)
#define PADH 40                   // half smem row stride (halves)

#define A32_BYTES (256 * PADK * 4)    // 40960 per stage (fp32 A)
#define A16_BYTES (256 * PADH * 2)    // 20480 per stage (half A)
#define B16_BYTES (128 * PADH * 2)    // 10240 per stage
#define SMEM1_BYTES (2 * A32_BYTES + 2 * B16_BYTES)   // 102400 (GEMM-1)
#define SMEM2_BYTES (2 * A16_BYTES + 2 * B16_BYTES)   // 61440  (GEMM-2)

// ---- scratch (device globals; no allocation allowed) ----
__device__ float  g_bcat[NCAT];
__device__ __half g_vh[(size_t)MROWS * CHN];    // value tensor, half
__device__ float  g_om[(size_t)MROWS * 128];    // offset(72)+mask(36)+pad, fp32
__device__ __half g_smp[(size_t)MROWS * CHN];
__device__ __half g_bp1[NCAT * KDIM];   // GEMM-1 B, col-major [n][k], half
__device__ __half g_bp2[CHN * KDIM];    // GEMM-2 B, col-major [n][k], half

__device__ __forceinline__ void cpasync16(uint32_t dst, const void* src) {
    asm volatile("cp.async.ca.shared.global [%0], [%1], 16;"
                 :: "r"(dst), "l"(src));
}
__device__ __forceinline__ uint32_t pack_h2(float lo, float hi) {
    uint32_t r;
    asm("cvt.rn.f16x2.f32 %0, %1, %2;" : "=r"(r) : "f"(hi), "f"(lo));
    return r;
}

// ---------------------------------------------------------------------------
// Pack weights to half (col-major [n][k]) + concat biases (fp32).
// ---------------------------------------------------------------------------
__global__ void pack_weights(const float* __restrict__ wv, const float* __restrict__ bv,
                             const float* __restrict__ wo, const float* __restrict__ bo,
                             const float* __restrict__ wm, const float* __restrict__ bm,
                             const float* __restrict__ wout)
{
    int idx = blockIdx.x * 256 + threadIdx.x;
    if (idx < NCAT * KDIM) {
        int n = idx >> 8, k = idx & 255;
        float val = 0.f;
        if (n < 256)      val = wv[k * 256 + n];
        else if (n < 328) val = wo[k * 72 + (n - 256)];
        else if (n < 364) val = wm[k * 36 + (n - 328)];
        g_bp1[idx] = __float2half_rn(val);
    } else if (idx < NCAT * KDIM + CHN * KDIM) {
        int j = idx - NCAT * KDIM;
        int n = j >> 8, k = j & 255;
        g_bp2[j] = __float2half_rn(wout[k * 256 + n]);
    } else if (idx < NCAT * KDIM + CHN * KDIM + NCAT) {
        int c = idx - (NCAT * KDIM + CHN * KDIM);
        float val = 0.f;
        if (c < 256)      val = bv[c];
        else if (c < 328) val = bo[c - 256];
        else if (c < 364) val = bm[c - 328];
        g_bcat[c] = val;
    }
}

// ===========================================================================
// GEMM core (R10-proven best): fp16 m16n8k16, fp32 accum, cp.async
// double-buffered, one sync per 32-K chunk. CTA 256x128, 8 warps (4m x 2n).
// ===========================================================================
template<int HALF_A>
__device__ __forceinline__ void gemm_core(const void* Avp, const __half* Bb,
                                          char* smem, float acc[4][8][4])
{
    uint32_t sbase = (uint32_t)__cvta_generic_to_shared(smem);
    const int ABYTES = HALF_A ? A16_BYTES : A32_BYTES;
    int tid = threadIdx.x;
    int warp = tid >> 5, lane = tid & 31;
    int wmi = warp >> 1, wni = warp & 1;
    int gid = lane >> 2, tg = lane & 3;

    const float*  Af = (const float*)Avp;
    const __half* Ah = (const __half*)Avp;

    auto issue = [&](int c, int b) {
        uint32_t adst = sbase + (uint32_t)(b * ABYTES);
        uint32_t bdst = sbase + (uint32_t)(2 * ABYTES + b * B16_BYTES);
        if (HALF_A) {
#pragma unroll
            for (int j = 0; j < 4; ++j) {
                int s = j * 256 + tid;
                int r = s >> 2, q = (s & 3) * 8;
                cpasync16(adst + (uint32_t)(r * PADH + q) * 2,
                          Ah + (size_t)r * KDIM + c * 32 + q);
            }
        } else {
            int r0 = tid >> 3, q0 = (tid & 7) * 4;
#pragma unroll
            for (int j = 0; j < 8; ++j) {
                int r = r0 + j * 32;
                cpasync16(adst + (uint32_t)(r * PADK + q0) * 4,
                          Af + (size_t)r * KDIM + c * 32 + q0);
            }
        }
#pragma unroll
        for (int j = 0; j < 2; ++j) {
            int s = j * 256 + tid;
            int r = s >> 2, q = (s & 3) * 8;
            cpasync16(bdst + (uint32_t)(r * PADH + q) * 2,
                      Bb + (size_t)r * KDIM + c * 32 + q);
        }
        asm volatile("cp.async.commit_group;" ::: "memory");
    };

    issue(0, 0);

    for (int c = 0; c < 8; ++c) {
        int b = c & 1;
        asm volatile("cp.async.wait_group 0;" ::: "memory");
        __syncthreads();
        if (c < 7) issue(c + 1, b ^ 1);

        const float*  As32 = (const float*)(smem + b * ABYTES);
        const __half* As16 = (const __half*)(smem + b * ABYTES);
        const __half* Bs   = (const __half*)(smem + 2 * ABYTES + b * B16_BYTES);

#pragma unroll
        for (int ks = 0; ks < 2; ++ks) {
            int kb = ks * 16;
            uint32_t a[4][4], bf[8][2];
#pragma unroll
            for (int mt = 0; mt < 4; ++mt) {
                int row = wmi * 64 + mt * 16;
                if (HALF_A) {
                    a[mt][0] = *(const uint32_t*)&As16[(row + gid)     * PADH + kb + 2 * tg];
                    a[mt][1] = *(const uint32_t*)&As16[(row + gid + 8) * PADH + kb + 2 * tg];
                    a[mt][2] = *(const uint32_t*)&As16[(row + gid)     * PADH + kb + 2 * tg + 8];
                    a[mt][3] = *(const uint32_t*)&As16[(row + gid + 8) * PADH + kb + 2 * tg + 8];
                } else {
                    float2 e0 = *(const float2*)&As32[(row + gid)     * PADK + kb + 2 * tg];
                    float2 e1 = *(const float2*)&As32[(row + gid + 8) * PADK + kb + 2 * tg];
                    float2 e2 = *(const float2*)&As32[(row + gid)     * PADK + kb + 2 * tg + 8];
                    float2 e3 = *(const float2*)&As32[(row + gid + 8) * PADK + kb + 2 * tg + 8];
                    a[mt][0] = pack_h2(e0.x, e0.y);
                    a[mt][1] = pack_h2(e1.x, e1.y);
                    a[mt][2] = pack_h2(e2.x, e2.y);
                    a[mt][3] = pack_h2(e3.x, e3.y);
                }
            }
#pragma unroll
            for (int nt = 0; nt < 8; ++nt) {
                int n = wni * 64 + nt * 8 + gid;
                bf[nt][0] = *(const uint32_t*)&Bs[n * PADH + kb + 2 * tg];
                bf[nt][1] = *(const uint32_t*)&Bs[n * PADH + kb + 2 * tg + 8];
            }
#pragma unroll
            for (int mt = 0; mt < 4; ++mt)
#pragma unroll
                for (int nt = 0; nt < 8; ++nt) {
                    asm volatile(
                        "mma.sync.aligned.m16n8k16.row.col.f32.f16.f16.f32 "
                        "{%0,%1,%2,%3}, {%4,%5,%6,%7}, {%8,%9}, {%0,%1,%2,%3};"
                        : "+f"(acc[mt][nt][0]), "+f"(acc[mt][nt][1]),
                          "+f"(acc[mt][nt][2]), "+f"(acc[mt][nt][3])
                        : "r"(a[mt][0]), "r"(a[mt][1]), "r"(a[mt][2]), "r"(a[mt][3]),
                          "r"(bf[nt][0]), "r"(bf[nt][1]));
                }
        }
    }
}

// ---------------------------------------------------------------------------
// GEMM-1: x(M,256) fp32 @ bp1 half -> N-tiles 0-1 -> g_vh half; tile 2 -> g_om.
// ---------------------------------------------------------------------------
__global__ __launch_bounds__(256) void gemm1(const float* __restrict__ A,
                                             const __half* __restrict__ Bh,
                                             const float* __restrict__ bias,
                                             __half* __restrict__ vh,
                                             float* __restrict__ om)
{
    extern __shared__ char smem[];
    float acc[4][8][4];
#pragma unroll
    for (int mt = 0; mt < 4; ++mt)
#pragma unroll
        for (int nt = 0; nt < 8; ++nt)
#pragma unroll
            for (int i = 0; i < 4; ++i) acc[mt][nt][i] = 0.f;

    gemm_core<0>(A + (size_t)blockIdx.y * 256 * KDIM,
                 Bh + (size_t)blockIdx.x * 128 * KDIM, smem, acc);

    int tid = threadIdx.x;
    int warp = tid >> 5, lane = tid & 31;
    int wmi = warp >> 1, wni = warp & 1;
    int gid = lane >> 2, tg = lane & 3;
    bool is_val = (blockIdx.x < 2);

#pragma unroll
    for (int mt = 0; mt < 4; ++mt) {
#pragma unroll
        for (int i = 0; i < 2; ++i) {
            size_t row = (size_t)blockIdx.y * 256 + wmi * 64 + mt * 16 + gid + i * 8;
#pragma unroll
            for (int nt = 0; nt < 8; ++nt) {
                int col = blockIdx.x * 128 + wni * 64 + nt * 8 + 2 * tg;
                float ox = acc[mt][nt][2 * i + 0] + bias[col + 0];
                float oy = acc[mt][nt][2 * i + 1] + bias[col + 1];
                if (is_val) {
                    *(uint32_t*)(vh + row * CHN + col) = pack_h2(ox, oy);
                } else {
                    *(float2*)(om + row * 128 + (col - 256)) = make_float2(ox, oy);
                }
            }
        }
    }
}

// ---------------------------------------------------------------------------
// GEMM-2: smp(M,256) half @ bp2 half + b_out -> out fp32 (ld 256)
// ---------------------------------------------------------------------------
__global__ __launch_bounds__(256) void gemm2(const __half* __restrict__ A,
                                             const __half* __restrict__ Bh,
                                             const float* __restrict__ bias,
                                             float* __restrict__ C)
{
    extern __shared__ char smem[];
    float acc[4][8][4];
#pragma unroll
    for (int mt = 0; mt < 4; ++mt)
#pragma unroll
        for (int nt = 0; nt < 8; ++nt)
#pragma unroll
            for (int i = 0; i < 4; ++i) acc[mt][nt][i] = 0.f;

    gemm_core<1>(A + (size_t)blockIdx.y * 256 * KDIM,
                 Bh + (size_t)blockIdx.x * 128 * KDIM, smem, acc);

    int tid = threadIdx.x;
    int warp = tid >> 5, lane = tid & 31;
    int wmi = warp >> 1, wni = warp & 1;
    int gid = lane >> 2, tg = lane & 3;

#pragma unroll
    for (int mt = 0; mt < 4; ++mt) {
#pragma unroll
        for (int i = 0; i < 2; ++i) {
            size_t row = (size_t)blockIdx.y * 256 + wmi * 64 + mt * 16 + gid + i * 8;
            float* Crow = C + row * (size_t)CHN;
#pragma unroll
            for (int nt = 0; nt < 8; ++nt) {
                int col = blockIdx.x * 128 + wni * 64 + nt * 8 + 2 * tg;
                float2 o;
                o.x = acc[mt][nt][2 * i + 0] + bias[col + 0];
                o.y = acc[mt][nt][2 * i + 1] + bias[col + 1];
                *(float2*)(&Crow[col]) = o;
            }
        }
    }
}

// ---------------------------------------------------------------------------
// DCNv4 sampling with PARALLEL per-pixel weight folding. 4 queries/block.
// Stage A (144 thr): per (q,g,p) store x0,y0,wx,wy,m.
// Stage F (256 thr, 16 per (q,g)): gather-style fold — each thread computes
//   3-4 of the 49 lattice pixel weights by summing the 9 points' contributions
//   in fixed p-order (deterministic; pixel out-of-bounds -> weight 0).
// Stage C (8 warps, 2 groups each): ballot/popc compaction to (W, offset) list.
// Gather (256 thr): list walk, 1 x LDG.64 + 4 FMA per entry (~18 vs 36 reads).
// ---------------------------------------------------------------------------
__global__ __launch_bounds__(256) void dcn_sample(const __half* __restrict__ vh,
                                                  const float* __restrict__ om,
                                                  __half* __restrict__ smp)
{
    int tid = threadIdx.x;
    int qbase = blockIdx.x * 4;

    __shared__ int   s_x0[4][4][9];
    __shared__ int   s_y0[4][4][9];
    __shared__ float s_wx[4][4][9];
    __shared__ float s_wy[4][4][9];
    __shared__ float s_m [4][4][9];
    __shared__ float s_grid[4][4][49];
    __shared__ float s_cw[4][4][36];
    __shared__ int   s_co[4][4][36];
    __shared__ int   s_cnt[4][4];

    // Stage A
    if (tid < 144) {
        int qq = tid / 36, u = tid % 36;
        int g = u / 9, p = u % 9;
        int q = qbase + qq;
        int hw = q & 4095, h = hw >> 6, w = hw & 63;
        const float* row = om + (size_t)q * 128;
        float ox = row[g * 18 + p * 2];
        float oy = row[g * 18 + p * 2 + 1];
        float m  = row[72 + g * 9 + p];

        int ix = p / 3, iy = p % 3;
        float gx = (float)(w + ix - 1) + ox;
        float gy = (float)(h + iy - 1) + oy;

        float x0f = floorf(gx), y0f = floorf(gy);
        s_x0[qq][g][p] = (int)x0f;
        s_y0[qq][g][p] = (int)y0f;
        s_wx[qq][g][p] = gx - x0f;
        s_wy[qq][g][p] = gy - y0f;
        s_m [qq][g][p] = m;
    }
    __syncthreads();

    // Stage F: fold. 16 threads per (q,g); each handles slots tsub + 16*j.
    {
        int gi = tid >> 4, tsub = tid & 15;
        int qq = gi >> 2, g = gi & 3;
        int q = qbase + qq;
        int hw = q & 4095, h = hw >> 6, w = hw & 63;

        int   px0[9], py0[9];
        float pwx[9], pwy[9], pm[9];
#pragma unroll
        for (int p = 0; p < 9; ++p) {
            px0[p] = s_x0[qq][g][p];
            py0[p] = s_y0[qq][g][p];
            pwx[p] = s_wx[qq][g][p];
            pwy[p] = s_wy[qq][g][p];
            pm [p] = s_m [qq][g][p];
        }
#pragma unroll
        for (int j = 0; j < 4; ++j) {
            int e = tsub + 16 * j;
            if (e < 49) {
                int dy = e / 7, dx = e % 7;
                int px = w - 3 + dx, py = h - 3 + dy;
                float W = 0.f;
#pragma unroll
                for (int p = 0; p < 9; ++p) {
                    float cx = (px == px0[p]) ? (1.f - pwx[p])
                             : ((px == px0[p] + 1) ? pwx[p] : 0.f);
                    float cy = (py == py0[p]) ? (1.f - pwy[p])
                             : ((py == py0[p] + 1) ? pwy[p] : 0.f);
                    W += cx * cy * pm[p];
                }
                if (px < 0 || px >= WWD || py < 0 || py >= HH) W = 0.f;
                s_grid[qq][g][e] = W;
            }
        }
    }
    __syncthreads();

    // Stage C: compaction. Warp k handles groups 2k, 2k+1.
    {
        int warp = tid >> 5, lane = tid & 31;
        for (int k = 0; k < 2; ++k) {
            int gi = warp * 2 + k;
            int qq = gi >> 2, g = gi & 3;
            int q = qbase + qq;
            int hw = q & 4095, h = hw >> 6, w = hw & 63;
            int cnt = 0;
            for (int base = 0; base < 49; base += 32) {
                int e = base + lane;
                float W = (e < 49) ? s_grid[qq][g][e] : 0.f;
                bool nz = (W != 0.f);
                unsigned bal = __ballot_sync(0xffffffffu, nz);
                int pos = cnt + __popc(bal & ((1u << lane) - 1u));
                if (nz) {
                    int dy = e / 7, dx = e % 7;
                    s_cw[qq][g][pos] = W;
                    s_co[qq][g][pos] = ((h - 3 + dy) * WWD + (w - 3 + dx)) * (CHN * 2);
                }
                cnt += __popc(bal);
            }
            if (lane == 0) s_cnt[qq][g] = cnt;
        }
    }
    __syncthreads();

    // Gather
    int qi = tid >> 6;
    int s  = tid & 63;
    int g  = s >> 4;
    int c4 = s & 15;
    int q = qbase + qi;
    int n = q >> 12;

    const char* vb = (const char*)(vh + (size_t)(n * LQ) * CHN + g * 64 + c4 * 4);
    int cnt = s_cnt[qi][g];

    float acc0 = 0.f, acc1 = 0.f, acc2 = 0.f, acc3 = 0.f;
    for (int i = 0; i < cnt; ++i) {
        float W = s_cw[qi][g][i];
        int   O = s_co[qi][g][i];
        uint2 r = *(const uint2*)(vb + O);
        float2 f0 = __half22float2(*(__half2*)&r.x);
        float2 f1 = __half22float2(*(__half2*)&r.y);
        acc0 = fmaf(W, f0.x, acc0); acc1 = fmaf(W, f0.y, acc1);
        acc2 = fmaf(W, f1.x, acc2); acc3 = fmaf(W, f1.y, acc3);
    }

    uint2 o;
    o.x = pack_h2(acc0, acc1);
    o.y = pack_h2(acc2, acc3);
    *(uint2*)(smp + (size_t)q * CHN + g * 64 + c4 * 4) = o;
}

// ---------------------------------------------------------------------------
extern "C" void kernel_launch(void* const* d_in, const int* in_sizes, int n_in,
                              void* d_out, int out_size)
{
    const float* x        = (const float*)d_in[0];
    const float* w_value  = (const float*)d_in[1];
    const float* b_value  = (const float*)d_in[2];
    const float* w_offset = (const float*)d_in[3];
    const float* b_offset = (const float*)d_in[4];
    const float* w_mask   = (const float*)d_in[5];
    const float* b_mask   = (const float*)d_in[6];
    const float* w_out    = (const float*)d_in[7];
    const float* b_out    = (const float*)d_in[8];
    float* out = (float*)d_out;

    float *bcat, *om;
    __half *vh, *smp, *bp1, *bp2;
    cudaGetSymbolAddress((void**)&vh,   g_vh);
    cudaGetSymbolAddress((void**)&om,   g_om);
    cudaGetSymbolAddress((void**)&smp,  g_smp);
    cudaGetSymbolAddress((void**)&bcat, g_bcat);
    cudaGetSymbolAddress((void**)&bp1,  g_bp1);
    cudaGetSymbolAddress((void**)&bp2,  g_bp2);

    cudaFuncSetAttribute(gemm1, cudaFuncAttributeMaxDynamicSharedMemorySize,
                         SMEM1_BYTES);
    cudaFuncSetAttribute(gemm2, cudaFuncAttributeMaxDynamicSharedMemorySize,
                         SMEM2_BYTES);

    int pack_elems = NCAT * KDIM + CHN * KDIM + NCAT;
    pack_weights<<<(pack_elems + 255) / 256, 256>>>(w_value, b_value, w_offset,
                                                    b_offset, w_mask, b_mask, w_out);

    // GEMM-1: x fp32 @ bp1 half -> vh (half) + om (fp32)
    gemm1<<<dim3(NCAT / 128, MROWS / 256), 256, SMEM1_BYTES>>>(x, bp1, bcat, vh, om);

    // DCNv4 sampling (parallel weight-folded gathers) -> smp half
    dcn_sample<<<MROWS / 4, 256>>>(vh, om, smp);

    // GEMM-2: smp half @ w_out half + b_out -> out fp32
    gemm2<<<dim3(CHN / 128, MROWS / 256), 256, SMEM2_BYTES>>>(smp, bp2, b_out, out);
}

// round 17
// speedup vs baseline: 1.5989x; 1.5989x over previous
#include <cuda_runtime.h>
#include <cuda_fp16.h>
#include <cstdint>

#define NB   8
#define HH   64
#define WWD  64
#define LQ   4096
#define CHN  256
#define NCAT 384
#define MROWS (NB * LQ)           // 32768
#define KDIM 256
#define PADK 40                   // A fp32 smem row stride (floats)
#define PADH 40                   // half smem row stride (halves)

#define A32_BYTES (128 * PADK * 4)    // 20480 per stage (fp32 A, 128 rows)
#define A16_BYTES (128 * PADH * 2)    // 10240 per stage (half A)
#define B16_BYTES (128 * PADH * 2)    // 10240 per stage
#define SMEM1_BYTES (2 * A32_BYTES + 2 * B16_BYTES)   // 61440 (GEMM-1)
#define SMEM2_BYTES (2 * A16_BYTES + 2 * B16_BYTES)   // 40960 (GEMM-2)

// ---- scratch (device globals; no allocation allowed) ----
__device__ float  g_bcat[NCAT];
__device__ __half g_vh[(size_t)MROWS * CHN];    // value tensor, half
__device__ float  g_om[(size_t)MROWS * 128];    // offset(72)+mask(36)+pad, fp32
__device__ __half g_smp[(size_t)MROWS * CHN];
__device__ __half g_bp1[NCAT * KDIM];   // GEMM-1 B, col-major [n][k], half
__device__ __half g_bp2[CHN * KDIM];    // GEMM-2 B, col-major [n][k], half

__device__ __forceinline__ void cpasync16(uint32_t dst, const void* src) {
    asm volatile("cp.async.ca.shared.global [%0], [%1], 16;"
                 :: "r"(dst), "l"(src));
}
__device__ __forceinline__ uint32_t pack_h2(float lo, float hi) {
    uint32_t r;
    asm("cvt.rn.f16x2.f32 %0, %1, %2;" : "=r"(r) : "f"(hi), "f"(lo));
    return r;
}

// ---------------------------------------------------------------------------
// Pack weights to half (col-major [n][k]) + concat biases (fp32).
// ---------------------------------------------------------------------------
__global__ void pack_weights(const float* __restrict__ wv, const float* __restrict__ bv,
                             const float* __restrict__ wo, const float* __restrict__ bo,
                             const float* __restrict__ wm, const float* __restrict__ bm,
                             const float* __restrict__ wout)
{
    int idx = blockIdx.x * 256 + threadIdx.x;
    if (idx < NCAT * KDIM) {
        int n = idx >> 8, k = idx & 255;
        float val = 0.f;
        if (n < 256)      val = wv[k * 256 + n];
        else if (n < 328) val = wo[k * 72 + (n - 256)];
        else if (n < 364) val = wm[k * 36 + (n - 328)];
        g_bp1[idx] = __float2half_rn(val);
    } else if (idx < NCAT * KDIM + CHN * KDIM) {
        int j = idx - NCAT * KDIM;
        int n = j >> 8, k = j & 255;
        g_bp2[j] = __float2half_rn(wout[k * 256 + n]);
    } else if (idx < NCAT * KDIM + CHN * KDIM + NCAT) {
        int c = idx - (NCAT * KDIM + CHN * KDIM);
        float val = 0.f;
        if (c < 256)      val = bv[c];
        else if (c < 328) val = bo[c - 256];
        else if (c < 364) val = bm[c - 328];
        g_bcat[c] = val;
    }
}

// ===========================================================================
// GEMM core: fp16 m16n8k16, fp32 accum, cp.async double-buffered, one sync
// per 32-K chunk. CTA tile 128x128, 8 warps (4m x 2n), warp tile 32x64.
// acc = 64 regs -> ~104 total -> 2 independent CTAs per SM (barrier
// interleaving: while one CTA waits on its chunk barrier the other computes).
// ===========================================================================
template<int HALF_A>
__device__ __forceinline__ void gemm_core(const void* Avp, const __half* Bb,
                                          char* smem, float acc[2][8][4])
{
    uint32_t sbase = (uint32_t)__cvta_generic_to_shared(smem);
    const int ABYTES = HALF_A ? A16_BYTES : A32_BYTES;
    int tid = threadIdx.x;
    int warp = tid >> 5, lane = tid & 31;
    int wmi = warp >> 1;          // 0..3 (M, 32-row tiles)
    int wni = warp & 1;           // 0..1 (N, 64-col tiles)
    int gid = lane >> 2, tg = lane & 3;

    const float*  Af = (const float*)Avp;
    const __half* Ah = (const __half*)Avp;

    auto issue = [&](int c, int b) {
        uint32_t adst = sbase + (uint32_t)(b * ABYTES);
        uint32_t bdst = sbase + (uint32_t)(2 * ABYTES + b * B16_BYTES);
        if (HALF_A) {
            // A: 128 rows x 32 halves = 512 x 16B; 2 per thread
#pragma unroll
            for (int j = 0; j < 2; ++j) {
                int s = j * 256 + tid;
                int r = s >> 2, q = (s & 3) * 8;
                cpasync16(adst + (uint32_t)(r * PADH + q) * 2,
                          Ah + (size_t)r * KDIM + c * 32 + q);
            }
        } else {
            // A: 128 rows x 32 floats = 1024 x 16B; 4 per thread
            int r0 = tid >> 3, q0 = (tid & 7) * 4;   // r0: 0..31
#pragma unroll
            for (int j = 0; j < 4; ++j) {
                int r = r0 + j * 32;
                cpasync16(adst + (uint32_t)(r * PADK + q0) * 4,
                          Af + (size_t)r * KDIM + c * 32 + q0);
            }
        }
        // B: 128 rows x 32 halves = 512 x 16B; 2 per thread
#pragma unroll
        for (int j = 0; j < 2; ++j) {
            int s = j * 256 + tid;
            int r = s >> 2, q = (s & 3) * 8;
            cpasync16(bdst + (uint32_t)(r * PADH + q) * 2,
                      Bb + (size_t)r * KDIM + c * 32 + q);
        }
        asm volatile("cp.async.commit_group;" ::: "memory");
    };

    issue(0, 0);

    for (int c = 0; c < 8; ++c) {
        int b = c & 1;
        asm volatile("cp.async.wait_group 0;" ::: "memory");
        __syncthreads();
        if (c < 7) issue(c + 1, b ^ 1);

        const float*  As32 = (const float*)(smem + b * ABYTES);
        const __half* As16 = (const __half*)(smem + b * ABYTES);
        const __half* Bs   = (const __half*)(smem + 2 * ABYTES + b * B16_BYTES);

#pragma unroll
        for (int ks = 0; ks < 2; ++ks) {
            int kb = ks * 16;
            uint32_t a[2][4], bf[8][2];
#pragma unroll
            for (int mt = 0; mt < 2; ++mt) {
                int row = wmi * 32 + mt * 16;
                if (HALF_A) {
                    a[mt][0] = *(const uint32_t*)&As16[(row + gid)     * PADH + kb + 2 * tg];
                    a[mt][1] = *(const uint32_t*)&As16[(row + gid + 8) * PADH + kb + 2 * tg];
                    a[mt][2] = *(const uint32_t*)&As16[(row + gid)     * PADH + kb + 2 * tg + 8];
                    a[mt][3] = *(const uint32_t*)&As16[(row + gid + 8) * PADH + kb + 2 * tg + 8];
                } else {
                    float2 e0 = *(const float2*)&As32[(row + gid)     * PADK + kb + 2 * tg];
                    float2 e1 = *(const float2*)&As32[(row + gid + 8) * PADK + kb + 2 * tg];
                    float2 e2 = *(const float2*)&As32[(row + gid)     * PADK + kb + 2 * tg + 8];
                    float2 e3 = *(const float2*)&As32[(row + gid + 8) * PADK + kb + 2 * tg + 8];
                    a[mt][0] = pack_h2(e0.x, e0.y);
                    a[mt][1] = pack_h2(e1.x, e1.y);
                    a[mt][2] = pack_h2(e2.x, e2.y);
                    a[mt][3] = pack_h2(e3.x, e3.y);
                }
            }
#pragma unroll
            for (int nt = 0; nt < 8; ++nt) {
                int n = wni * 64 + nt * 8 + gid;
                bf[nt][0] = *(const uint32_t*)&Bs[n * PADH + kb + 2 * tg];
                bf[nt][1] = *(const uint32_t*)&Bs[n * PADH + kb + 2 * tg + 8];
            }
#pragma unroll
            for (int mt = 0; mt < 2; ++mt)
#pragma unroll
                for (int nt = 0; nt < 8; ++nt) {
                    asm volatile(
                        "mma.sync.aligned.m16n8k16.row.col.f32.f16.f16.f32 "
                        "{%0,%1,%2,%3}, {%4,%5,%6,%7}, {%8,%9}, {%0,%1,%2,%3};"
                        : "+f"(acc[mt][nt][0]), "+f"(acc[mt][nt][1]),
                          "+f"(acc[mt][nt][2]), "+f"(acc[mt][nt][3])
                        : "r"(a[mt][0]), "r"(a[mt][1]), "r"(a[mt][2]), "r"(a[mt][3]),
                          "r"(bf[nt][0]), "r"(bf[nt][1]));
                }
        }
    }
}

// ---------------------------------------------------------------------------
// GEMM-1: x(M,256) fp32 @ bp1 half -> N-tiles 0-1 -> g_vh half; tile 2 -> g_om.
// ---------------------------------------------------------------------------
__global__ __launch_bounds__(256, 2) void gemm1(const float* __restrict__ A,
                                                const __half* __restrict__ Bh,
                                                const float* __restrict__ bias,
                                                __half* __restrict__ vh,
                                                float* __restrict__ om)
{
    extern __shared__ char smem[];
    float acc[2][8][4];
#pragma unroll
    for (int mt = 0; mt < 2; ++mt)
#pragma unroll
        for (int nt = 0; nt < 8; ++nt)
#pragma unroll
            for (int i = 0; i < 4; ++i) acc[mt][nt][i] = 0.f;

    gemm_core<0>(A + (size_t)blockIdx.y * 128 * KDIM,
                 Bh + (size_t)blockIdx.x * 128 * KDIM, smem, acc);

    int tid = threadIdx.x;
    int warp = tid >> 5, lane = tid & 31;
    int wmi = warp >> 1, wni = warp & 1;
    int gid = lane >> 2, tg = lane & 3;
    bool is_val = (blockIdx.x < 2);

#pragma unroll
    for (int mt = 0; mt < 2; ++mt) {
#pragma unroll
        for (int i = 0; i < 2; ++i) {
            size_t row = (size_t)blockIdx.y * 128 + wmi * 32 + mt * 16 + gid + i * 8;
#pragma unroll
            for (int nt = 0; nt < 8; ++nt) {
                int col = blockIdx.x * 128 + wni * 64 + nt * 8 + 2 * tg;
                float ox = acc[mt][nt][2 * i + 0] + bias[col + 0];
                float oy = acc[mt][nt][2 * i + 1] + bias[col + 1];
                if (is_val) {
                    *(uint32_t*)(vh + row * CHN + col) = pack_h2(ox, oy);
                } else {
                    *(float2*)(om + row * 128 + (col - 256)) = make_float2(ox, oy);
                }
            }
        }
    }
}

// ---------------------------------------------------------------------------
// GEMM-2: smp(M,256) half @ bp2 half + b_out -> out fp32 (ld 256)
// ---------------------------------------------------------------------------
__global__ __launch_bounds__(256, 2) void gemm2(const __half* __restrict__ A,
                                                const __half* __restrict__ Bh,
                                                const float* __restrict__ bias,
                                                float* __restrict__ C)
{
    extern __shared__ char smem[];
    float acc[2][8][4];
#pragma unroll
    for (int mt = 0; mt < 2; ++mt)
#pragma unroll
        for (int nt = 0; nt < 8; ++nt)
#pragma unroll
            for (int i = 0; i < 4; ++i) acc[mt][nt][i] = 0.f;

    gemm_core<1>(A + (size_t)blockIdx.y * 128 * KDIM,
                 Bh + (size_t)blockIdx.x * 128 * KDIM, smem, acc);

    int tid = threadIdx.x;
    int warp = tid >> 5, lane = tid & 31;
    int wmi = warp >> 1, wni = warp & 1;
    int gid = lane >> 2, tg = lane & 3;

#pragma unroll
    for (int mt = 0; mt < 2; ++mt) {
#pragma unroll
        for (int i = 0; i < 2; ++i) {
            size_t row = (size_t)blockIdx.y * 128 + wmi * 32 + mt * 16 + gid + i * 8;
            float* Crow = C + row * (size_t)CHN;
#pragma unroll
            for (int nt = 0; nt < 8; ++nt) {
                int col = blockIdx.x * 128 + wni * 64 + nt * 8 + 2 * tg;
                float2 o;
                o.x = acc[mt][nt][2 * i + 0] + bias[col + 0];
                o.y = acc[mt][nt][2 * i + 1] + bias[col + 1];
                *(float2*)(&Crow[col]) = o;
            }
        }
    }
}

// ---------------------------------------------------------------------------
// DCNv4 bilinear sampling on HALF values (exact R10 version, best measured).
// ---------------------------------------------------------------------------
__global__ __launch_bounds__(256) void dcn_sample(const __half* __restrict__ vh,
                                                  const float* __restrict__ om,
                                                  __half* __restrict__ smp)
{
    int tid = threadIdx.x;
    int qbase = blockIdx.x * 4;

    __shared__ float4 s_wgt[4][4][9];
    __shared__ int4   s_idx[4][4][9];

    if (tid < 144) {
        int qq = tid / 36, u = tid % 36;
        int g = u / 9, p = u % 9;
        int q = qbase + qq;
        int hw = q & 4095, h = hw >> 6, w = hw & 63;
        const float* row = om + (size_t)q * 128;
        float ox = row[g * 18 + p * 2];
        float oy = row[g * 18 + p * 2 + 1];
        float m  = row[72 + g * 9 + p];

        int ix = p / 3, iy = p % 3;
        float gx = (float)(w + ix - 1) + ox;
        float gy = (float)(h + iy - 1) + oy;

        float x0f = floorf(gx), y0f = floorf(gy);
        int x0 = (int)x0f, y0 = (int)y0f;
        float wx = gx - x0f, wy = gy - y0f;

        float vx0 = (x0 >= 0 && x0 < WWD) ? 1.f : 0.f;
        float vx1 = (x0 + 1 >= 0 && x0 + 1 < WWD) ? 1.f : 0.f;
        float vy0 = (y0 >= 0 && y0 < HH) ? 1.f : 0.f;
        float vy1 = (y0 + 1 >= 0 && y0 + 1 < HH) ? 1.f : 0.f;

        float4 W;
        W.x = (1.f - wx) * (1.f - wy) * m * vx0 * vy0;
        W.y = wx * (1.f - wy) * m * vx1 * vy0;
        W.z = (1.f - wx) * wy * m * vx0 * vy1;
        W.w = wx * wy * m * vx1 * vy1;

        int x0c = min(max(x0, 0), WWD - 1);
        int x1c = min(max(x0 + 1, 0), WWD - 1);
        int y0c = min(max(y0, 0), HH - 1);
        int y1c = min(max(y0 + 1, 0), HH - 1);

        int4 O;
        O.x = (y0c * WWD + x0c) * (CHN * 2);
        O.y = (y0c * WWD + x1c) * (CHN * 2);
        O.z = (y1c * WWD + x0c) * (CHN * 2);
        O.w = (y1c * WWD + x1c) * (CHN * 2);

        s_wgt[qq][g][p] = W;
        s_idx[qq][g][p] = O;
    }
    __syncthreads();

    int qi = tid >> 6;
    int s  = tid & 63;
    int g  = s >> 4;
    int c4 = s & 15;
    int q = qbase + qi;
    int n = q >> 12;

    const char* vb = (const char*)(vh + (size_t)(n * LQ) * CHN + g * 64 + c4 * 4);

    float acc0 = 0.f, acc1 = 0.f, acc2 = 0.f, acc3 = 0.f;
#pragma unroll
    for (int p = 0; p < 9; ++p) {
        float4 W = s_wgt[qi][g][p];
        int4   O = s_idx[qi][g][p];

        uint2 r00 = *(const uint2*)(vb + O.x);
        uint2 r10 = *(const uint2*)(vb + O.y);
        uint2 r01 = *(const uint2*)(vb + O.z);
        uint2 r11 = *(const uint2*)(vb + O.w);

        float2 a0, a1;
        a0 = __half22float2(*(__half2*)&r00.x); a1 = __half22float2(*(__half2*)&r00.y);
        acc0 = fmaf(W.x, a0.x, acc0); acc1 = fmaf(W.x, a0.y, acc1);
        acc2 = fmaf(W.x, a1.x, acc2); acc3 = fmaf(W.x, a1.y, acc3);
        a0 = __half22float2(*(__half2*)&r10.x); a1 = __half22float2(*(__half2*)&r10.y);
        acc0 = fmaf(W.y, a0.x, acc0); acc1 = fmaf(W.y, a0.y, acc1);
        acc2 = fmaf(W.y, a1.x, acc2); acc3 = fmaf(W.y, a1.y, acc3);
        a0 = __half22float2(*(__half2*)&r01.x); a1 = __half22float2(*(__half2*)&r01.y);
        acc0 = fmaf(W.z, a0.x, acc0); acc1 = fmaf(W.z, a0.y, acc1);
        acc2 = fmaf(W.z, a1.x, acc2); acc3 = fmaf(W.z, a1.y, acc3);
        a0 = __half22float2(*(__half2*)&r11.x); a1 = __half22float2(*(__half2*)&r11.y);
        acc0 = fmaf(W.w, a0.x, acc0); acc1 = fmaf(W.w, a0.y, acc1);
        acc2 = fmaf(W.w, a1.x, acc2); acc3 = fmaf(W.w, a1.y, acc3);
    }

    uint2 o;
    o.x = pack_h2(acc0, acc1);
    o.y = pack_h2(acc2, acc3);
    *(uint2*)(smp + (size_t)q * CHN + g * 64 + c4 * 4) = o;
}

// ---------------------------------------------------------------------------
extern "C" void kernel_launch(void* const* d_in, const int* in_sizes, int n_in,
                              void* d_out, int out_size)
{
    const float* x        = (const float*)d_in[0];
    const float* w_value  = (const float*)d_in[1];
    const float* b_value  = (const float*)d_in[2];
    const float* w_offset = (const float*)d_in[3];
    const float* b_offset = (const float*)d_in[4];
    const float* w_mask   = (const float*)d_in[5];
    const float* b_mask   = (const float*)d_in[6];
    const float* w_out    = (const float*)d_in[7];
    const float* b_out    = (const float*)d_in[8];
    float* out = (float*)d_out;

    float *bcat, *om;
    __half *vh, *smp, *bp1, *bp2;
    cudaGetSymbolAddress((void**)&vh,   g_vh);
    cudaGetSymbolAddress((void**)&om,   g_om);
    cudaGetSymbolAddress((void**)&smp,  g_smp);
    cudaGetSymbolAddress((void**)&bcat, g_bcat);
    cudaGetSymbolAddress((void**)&bp1,  g_bp1);
    cudaGetSymbolAddress((void**)&bp2,  g_bp2);

    cudaFuncSetAttribute(gemm1, cudaFuncAttributeMaxDynamicSharedMemorySize,
                         SMEM1_BYTES);
    cudaFuncSetAttribute(gemm2, cudaFuncAttributeMaxDynamicSharedMemorySize,
                         SMEM2_BYTES);

    int pack_elems = NCAT * KDIM + CHN * KDIM + NCAT;
    pack_weights<<<(pack_elems + 255) / 256, 256>>>(w_value, b_value, w_offset,
                                                    b_offset, w_mask, b_mask, w_out);

    // GEMM-1: x fp32 @ bp1 half -> vh (half) + om (fp32)
    gemm1<<<dim3(NCAT / 128, MROWS / 128), 256, SMEM1_BYTES>>>(x, bp1, bcat, vh, om);

    // DCNv4 sampling on half values -> smp half
    dcn_sample<<<MROWS / 4, 256>>>(vh, om, smp);

    // GEMM-2: smp half @ w_out half + b_out -> out fp32
    gemm2<<<dim3(CHN / 128, MROWS / 128), 256, SMEM2_BYTES>>>(smp, bp2, b_out, out);
}